// round 4
// baseline (speedup 1.0000x reference)
#include <cuda_runtime.h>
#include <cuda_bf16.h>
#include <math.h>

#define BB 4
#define TT 2048
#define DD 1024
#define HH 16
#define HD 64
#define MM (BB * TT)   // 8192 rows

#define BM 64
#define BN 64
#define BK 16

// Scratch (no cudaMalloc allowed)
__device__ float g_q[(size_t)MM * DD];
__device__ float g_k[(size_t)MM * DD];
__device__ float g_v[(size_t)MM * DD];
__device__ float g_ctx[(size_t)MM * DD];
__device__ float g_attn[(size_t)BB * HH * TT * TT];  // fallback if attn not in d_out

// ---------------------------------------------------------------------------
// C[M,N] = A[M,K] @ B[N,K]^T   (torch Linear: x @ W^T)
// 64x64 tile, 16x16 threads, 4x4 register blocking, float4 K-loads.
// ---------------------------------------------------------------------------
__global__ void __launch_bounds__(256)
gemm_abt(const float* __restrict__ A, const float* __restrict__ B,
         float* __restrict__ C, int K, int lda, int ldb, int ldc) {
    __shared__ float As[BK][BM];
    __shared__ float Bs[BK][BN];
    const int tx = threadIdx.x, ty = threadIdx.y;
    const int row0 = blockIdx.y * BM, col0 = blockIdx.x * BN;
    const int tid = ty * 16 + tx;
    const int lm = tid >> 2;            // 0..63
    const int lk = (tid & 3) * 4;       // 0,4,8,12
    float acc[4][4] = {};
    for (int k0 = 0; k0 < K; k0 += BK) {
        float4 a4 = *(const float4*)&A[(size_t)(row0 + lm) * lda + k0 + lk];
        float4 b4 = *(const float4*)&B[(size_t)(col0 + lm) * ldb + k0 + lk];
        As[lk + 0][lm] = a4.x; As[lk + 1][lm] = a4.y;
        As[lk + 2][lm] = a4.z; As[lk + 3][lm] = a4.w;
        Bs[lk + 0][lm] = b4.x; Bs[lk + 1][lm] = b4.y;
        Bs[lk + 2][lm] = b4.z; Bs[lk + 3][lm] = b4.w;
        __syncthreads();
#pragma unroll
        for (int kk = 0; kk < BK; kk++) {
            float a[4], b[4];
#pragma unroll
            for (int i = 0; i < 4; i++) a[i] = As[kk][ty * 4 + i];
#pragma unroll
            for (int j = 0; j < 4; j++) b[j] = Bs[kk][tx * 4 + j];
#pragma unroll
            for (int i = 0; i < 4; i++)
#pragma unroll
                for (int j = 0; j < 4; j++) acc[i][j] = fmaf(a[i], b[j], acc[i][j]);
        }
        __syncthreads();
    }
#pragma unroll
    for (int i = 0; i < 4; i++)
#pragma unroll
        for (int j = 0; j < 4; j++)
            C[(size_t)(row0 + ty * 4 + i) * ldc + col0 + tx * 4 + j] = acc[i][j];
}

// ---------------------------------------------------------------------------
// Batched causal scores: S[b,h] = (q_h @ k_h^T) * 1/sqrt(HD). Masked entries
// (col > row) are never written — softmax never reads them and zeroes them.
// Fully-masked tiles early-exit.
// ---------------------------------------------------------------------------
__global__ void __launch_bounds__(256)
scores_kernel(const float* __restrict__ q, const float* __restrict__ k,
              float* __restrict__ attn) {
    const int row0 = blockIdx.y * BM, col0 = blockIdx.x * BN;
    if (col0 > row0 + BM - 1) return;       // entire tile above diagonal
    const int z = blockIdx.z;               // b*H + h
    const int b = z / HH, h = z % HH;
    const float* A = q + (size_t)b * TT * DD + h * HD;
    const float* Bp = k + (size_t)b * TT * DD + h * HD;
    float* C = attn + (size_t)z * TT * TT;

    __shared__ float As[BK][BM];
    __shared__ float Bs[BK][BN];
    const int tx = threadIdx.x, ty = threadIdx.y;
    const int tid = ty * 16 + tx;
    const int lm = tid >> 2;
    const int lk = (tid & 3) * 4;
    float acc[4][4] = {};
    for (int k0 = 0; k0 < HD; k0 += BK) {
        float4 a4 = *(const float4*)&A[(size_t)(row0 + lm) * DD + k0 + lk];
        float4 b4 = *(const float4*)&Bp[(size_t)(col0 + lm) * DD + k0 + lk];
        As[lk + 0][lm] = a4.x; As[lk + 1][lm] = a4.y;
        As[lk + 2][lm] = a4.z; As[lk + 3][lm] = a4.w;
        Bs[lk + 0][lm] = b4.x; Bs[lk + 1][lm] = b4.y;
        Bs[lk + 2][lm] = b4.z; Bs[lk + 3][lm] = b4.w;
        __syncthreads();
#pragma unroll
        for (int kk = 0; kk < BK; kk++) {
            float a[4], bb[4];
#pragma unroll
            for (int i = 0; i < 4; i++) a[i] = As[kk][ty * 4 + i];
#pragma unroll
            for (int j = 0; j < 4; j++) bb[j] = Bs[kk][tx * 4 + j];
#pragma unroll
            for (int i = 0; i < 4; i++)
#pragma unroll
                for (int j = 0; j < 4; j++) acc[i][j] = fmaf(a[i], bb[j], acc[i][j]);
        }
        __syncthreads();
    }
    const float scale = 0.125f;  // 1/sqrt(64)
#pragma unroll
    for (int i = 0; i < 4; i++) {
        int r = row0 + ty * 4 + i;
#pragma unroll
        for (int j = 0; j < 4; j++) {
            int c = col0 + tx * 4 + j;
            if (c <= r) C[(size_t)r * TT + c] = acc[i][j] * scale;
        }
    }
}

// ---------------------------------------------------------------------------
// Row softmax over the causal prefix; zeroes the masked suffix (cleans the
// 0xAA-poisoned output buffer). One block per (b,h,t) row.
// ---------------------------------------------------------------------------
__global__ void __launch_bounds__(256)
softmax_kernel(float* __restrict__ attn) {
    const int r = blockIdx.x;               // z*T + t
    const int t = r & (TT - 1);
    float* row = attn + (size_t)r * TT;
    const int tid = threadIdx.x;
    __shared__ float red[256];

    float m = -INFINITY;
    for (int j = tid; j <= t; j += 256) m = fmaxf(m, row[j]);
    red[tid] = m;
    __syncthreads();
    for (int s = 128; s > 0; s >>= 1) {
        if (tid < s) red[tid] = fmaxf(red[tid], red[tid + s]);
        __syncthreads();
    }
    const float rowmax = red[0];
    __syncthreads();

    float sum = 0.f;
    for (int j = tid; j <= t; j += 256) {
        float e = expf(row[j] - rowmax);
        row[j] = e;
        sum += e;
    }
    red[tid] = sum;
    __syncthreads();
    for (int s = 128; s > 0; s >>= 1) {
        if (tid < s) red[tid] += red[tid + s];
        __syncthreads();
    }
    const float inv = 1.0f / red[0];
    __syncthreads();

    for (int j = tid; j <= t; j += 256) row[j] *= inv;
    for (int j = t + 1 + tid; j < TT; j += 256) row[j] = 0.0f;
}

// ---------------------------------------------------------------------------
// Batched ctx = attn @ v. attn rows are zero beyond the diagonal, so the
// K loop is truncated to row0+BM (causal extent of this row tile).
// ---------------------------------------------------------------------------
__global__ void __launch_bounds__(256)
ctx_kernel(const float* __restrict__ attn, const float* __restrict__ v,
           float* __restrict__ ctx) {
    const int z = blockIdx.z;
    const int b = z / HH, h = z % HH;
    const int row0 = blockIdx.y * BM;       // gridDim.x == 1 (N = HD = 64)
    const float* A = attn + (size_t)z * TT * TT;          // [T,T], ld T
    const float* Bp = v + (size_t)b * TT * DD + h * HD;   // [T,HD], ld D
    float* C = ctx + (size_t)b * TT * DD + h * HD;        // ld D

    __shared__ float As[BK][BM];
    __shared__ float Bs[BK][BN];
    const int tx = threadIdx.x, ty = threadIdx.y;
    const int tid = ty * 16 + tx;
    const int lm = tid >> 2;
    const int lk = (tid & 3) * 4;
    const int Keff = row0 + BM;             // attn[r, j>r] == 0
    float acc[4][4] = {};
    for (int k0 = 0; k0 < Keff; k0 += BK) {
        float4 a4 = *(const float4*)&A[(size_t)(row0 + lm) * TT + k0 + lk];
        As[lk + 0][lm] = a4.x; As[lk + 1][lm] = a4.y;
        As[lk + 2][lm] = a4.z; As[lk + 3][lm] = a4.w;
        { // B: 16 k x 64 n, n-contiguous
            int kk = tid >> 4, n = (tid & 15) * 4;
            float4 b4 = *(const float4*)&Bp[(size_t)(k0 + kk) * DD + n];
            Bs[kk][n + 0] = b4.x; Bs[kk][n + 1] = b4.y;
            Bs[kk][n + 2] = b4.z; Bs[kk][n + 3] = b4.w;
        }
        __syncthreads();
#pragma unroll
        for (int kk = 0; kk < BK; kk++) {
            float a[4], bb[4];
#pragma unroll
            for (int i = 0; i < 4; i++) a[i] = As[kk][ty * 4 + i];
#pragma unroll
            for (int j = 0; j < 4; j++) bb[j] = Bs[kk][tx * 4 + j];
#pragma unroll
            for (int i = 0; i < 4; i++)
#pragma unroll
                for (int j = 0; j < 4; j++) acc[i][j] = fmaf(a[i], bb[j], acc[i][j]);
        }
        __syncthreads();
    }
#pragma unroll
    for (int i = 0; i < 4; i++)
#pragma unroll
        for (int j = 0; j < 4; j++)
            C[(size_t)(row0 + ty * 4 + i) * DD + tx * 4 + j] = acc[i][j];
}

// ---------------------------------------------------------------------------
extern "C" void kernel_launch(void* const* d_in, const int* in_sizes, int n_in,
                              void* d_out, int out_size) {
    const float* x  = (const float*)d_in[0];
    const float* Wq = (const float*)d_in[1];
    const float* Wk = (const float*)d_in[2];
    const float* Wv = (const float*)d_in[3];
    const float* Wo = (const float*)d_in[4];
    float* out = (float*)d_out;

    const size_t out_elems  = (size_t)BB * TT * DD;         // 8,388,608
    const size_t attn_elems = (size_t)BB * HH * TT * TT;    // 268,435,456

    float* attn;
    if ((size_t)out_size >= out_elems + attn_elems) {
        attn = out + out_elems;            // tuple (out, attn) flattened
    } else {
        float* p;
        cudaGetSymbolAddress((void**)&p, g_attn);
        attn = p;
    }
    float *q, *k, *v, *ctx;
    cudaGetSymbolAddress((void**)&q,   g_q);
    cudaGetSymbolAddress((void**)&k,   g_k);
    cudaGetSymbolAddress((void**)&v,   g_v);
    cudaGetSymbolAddress((void**)&ctx, g_ctx);

    dim3 blk(16, 16);
    dim3 gproj(DD / BN, MM / BM);       // 16 x 128
    gemm_abt<<<gproj, blk>>>(x, Wq, q, DD, DD, DD, DD);
    gemm_abt<<<gproj, blk>>>(x, Wk, k, DD, DD, DD, DD);
    gemm_abt<<<gproj, blk>>>(x, Wv, v, DD, DD, DD, DD);

    dim3 gsc(TT / BN, TT / BM, BB * HH);  // 32 x 32 x 64 (half early-exit)
    scores_kernel<<<gsc, blk>>>(q, k, attn);

    softmax_kernel<<<BB * HH * TT, 256>>>(attn);

    dim3 gctx(1, TT / BM, BB * HH);       // 1 x 32 x 64
    ctx_kernel<<<gctx, blk>>>(attn, v, ctx);

    gemm_abt<<<gproj, blk>>>(ctx, Wo, out, DD, DD, DD, DD);
}

// round 5
// speedup vs baseline: 1.0036x; 1.0036x over previous
#include <cuda_runtime.h>
#include <cuda_bf16.h>
#include <math.h>

#define BB 4
#define TT 2048
#define DD 1024
#define HH 16
#define HD 64
#define MM (BB * TT)   // 8192 rows

#define BM 64
#define BN 64
#define BK 16

// Scratch (no cudaMalloc allowed)
__device__ float g_q[(size_t)MM * DD];
__device__ float g_k[(size_t)MM * DD];
__device__ float g_v[(size_t)MM * DD];
__device__ float g_ctx[(size_t)MM * DD];
__device__ float g_attn[(size_t)BB * HH * TT * TT];  // fallback if attn not in d_out

// ---------------------------------------------------------------------------
// C[M,N] = A[M,K] @ B[N,K]^T   (torch Linear: x @ W^T)
// 64x64 tile, 16x16 threads, 4x4 register blocking, float4 K-loads.
// ---------------------------------------------------------------------------
__global__ void __launch_bounds__(256)
gemm_abt(const float* __restrict__ A, const float* __restrict__ B,
         float* __restrict__ C, int K, int lda, int ldb, int ldc) {
    __shared__ float As[BK][BM];
    __shared__ float Bs[BK][BN];
    const int tx = threadIdx.x, ty = threadIdx.y;
    const int row0 = blockIdx.y * BM, col0 = blockIdx.x * BN;
    const int tid = ty * 16 + tx;
    const int lm = tid >> 2;            // 0..63
    const int lk = (tid & 3) * 4;       // 0,4,8,12
    float acc[4][4] = {};
    for (int k0 = 0; k0 < K; k0 += BK) {
        float4 a4 = *(const float4*)&A[(size_t)(row0 + lm) * lda + k0 + lk];
        float4 b4 = *(const float4*)&B[(size_t)(col0 + lm) * ldb + k0 + lk];
        As[lk + 0][lm] = a4.x; As[lk + 1][lm] = a4.y;
        As[lk + 2][lm] = a4.z; As[lk + 3][lm] = a4.w;
        Bs[lk + 0][lm] = b4.x; Bs[lk + 1][lm] = b4.y;
        Bs[lk + 2][lm] = b4.z; Bs[lk + 3][lm] = b4.w;
        __syncthreads();
#pragma unroll
        for (int kk = 0; kk < BK; kk++) {
            float a[4], b[4];
#pragma unroll
            for (int i = 0; i < 4; i++) a[i] = As[kk][ty * 4 + i];
#pragma unroll
            for (int j = 0; j < 4; j++) b[j] = Bs[kk][tx * 4 + j];
#pragma unroll
            for (int i = 0; i < 4; i++)
#pragma unroll
                for (int j = 0; j < 4; j++) acc[i][j] = fmaf(a[i], b[j], acc[i][j]);
        }
        __syncthreads();
    }
#pragma unroll
    for (int i = 0; i < 4; i++)
#pragma unroll
        for (int j = 0; j < 4; j++)
            C[(size_t)(row0 + ty * 4 + i) * ldc + col0 + tx * 4 + j] = acc[i][j];
}

// ---------------------------------------------------------------------------
// Batched causal scores: S[b,h] = (q_h @ k_h^T) * 1/sqrt(HD). Masked entries
// (col > row) are never written — softmax never reads them and zeroes them.
// Fully-masked tiles early-exit.
// ---------------------------------------------------------------------------
__global__ void __launch_bounds__(256)
scores_kernel(const float* __restrict__ q, const float* __restrict__ k,
              float* __restrict__ attn) {
    const int row0 = blockIdx.y * BM, col0 = blockIdx.x * BN;
    if (col0 > row0 + BM - 1) return;       // entire tile above diagonal
    const int z = blockIdx.z;               // b*H + h
    const int b = z / HH, h = z % HH;
    const float* A = q + (size_t)b * TT * DD + h * HD;
    const float* Bp = k + (size_t)b * TT * DD + h * HD;
    float* C = attn + (size_t)z * TT * TT;

    __shared__ float As[BK][BM];
    __shared__ float Bs[BK][BN];
    const int tx = threadIdx.x, ty = threadIdx.y;
    const int tid = ty * 16 + tx;
    const int lm = tid >> 2;
    const int lk = (tid & 3) * 4;
    float acc[4][4] = {};
    for (int k0 = 0; k0 < HD; k0 += BK) {
        float4 a4 = *(const float4*)&A[(size_t)(row0 + lm) * DD + k0 + lk];
        float4 b4 = *(const float4*)&Bp[(size_t)(col0 + lm) * DD + k0 + lk];
        As[lk + 0][lm] = a4.x; As[lk + 1][lm] = a4.y;
        As[lk + 2][lm] = a4.z; As[lk + 3][lm] = a4.w;
        Bs[lk + 0][lm] = b4.x; Bs[lk + 1][lm] = b4.y;
        Bs[lk + 2][lm] = b4.z; Bs[lk + 3][lm] = b4.w;
        __syncthreads();
#pragma unroll
        for (int kk = 0; kk < BK; kk++) {
            float a[4], bb[4];
#pragma unroll
            for (int i = 0; i < 4; i++) a[i] = As[kk][ty * 4 + i];
#pragma unroll
            for (int j = 0; j < 4; j++) bb[j] = Bs[kk][tx * 4 + j];
#pragma unroll
            for (int i = 0; i < 4; i++)
#pragma unroll
                for (int j = 0; j < 4; j++) acc[i][j] = fmaf(a[i], bb[j], acc[i][j]);
        }
        __syncthreads();
    }
    const float scale = 0.125f;  // 1/sqrt(64)
#pragma unroll
    for (int i = 0; i < 4; i++) {
        int r = row0 + ty * 4 + i;
#pragma unroll
        for (int j = 0; j < 4; j++) {
            int c = col0 + tx * 4 + j;
            if (c <= r) C[(size_t)r * TT + c] = acc[i][j] * scale;
        }
    }
}

// ---------------------------------------------------------------------------
// Row softmax over the causal prefix; zeroes the masked suffix (cleans the
// 0xAA-poisoned output buffer). One block per (b,h,t) row.
// ---------------------------------------------------------------------------
__global__ void __launch_bounds__(256)
softmax_kernel(float* __restrict__ attn) {
    const int r = blockIdx.x;               // z*T + t
    const int t = r & (TT - 1);
    float* row = attn + (size_t)r * TT;
    const int tid = threadIdx.x;
    __shared__ float red[256];

    float m = -INFINITY;
    for (int j = tid; j <= t; j += 256) m = fmaxf(m, row[j]);
    red[tid] = m;
    __syncthreads();
    for (int s = 128; s > 0; s >>= 1) {
        if (tid < s) red[tid] = fmaxf(red[tid], red[tid + s]);
        __syncthreads();
    }
    const float rowmax = red[0];
    __syncthreads();

    float sum = 0.f;
    for (int j = tid; j <= t; j += 256) {
        float e = expf(row[j] - rowmax);
        row[j] = e;
        sum += e;
    }
    red[tid] = sum;
    __syncthreads();
    for (int s = 128; s > 0; s >>= 1) {
        if (tid < s) red[tid] += red[tid + s];
        __syncthreads();
    }
    const float inv = 1.0f / red[0];
    __syncthreads();

    for (int j = tid; j <= t; j += 256) row[j] *= inv;
    for (int j = t + 1 + tid; j < TT; j += 256) row[j] = 0.0f;
}

// ---------------------------------------------------------------------------
// Batched ctx = attn @ v. attn rows are zero beyond the diagonal, so the
// K loop is truncated to row0+BM (causal extent of this row tile).
// ---------------------------------------------------------------------------
__global__ void __launch_bounds__(256)
ctx_kernel(const float* __restrict__ attn, const float* __restrict__ v,
           float* __restrict__ ctx) {
    const int z = blockIdx.z;
    const int b = z / HH, h = z % HH;
    const int row0 = blockIdx.y * BM;       // gridDim.x == 1 (N = HD = 64)
    const float* A = attn + (size_t)z * TT * TT;          // [T,T], ld T
    const float* Bp = v + (size_t)b * TT * DD + h * HD;   // [T,HD], ld D
    float* C = ctx + (size_t)b * TT * DD + h * HD;        // ld D

    __shared__ float As[BK][BM];
    __shared__ float Bs[BK][BN];
    const int tx = threadIdx.x, ty = threadIdx.y;
    const int tid = ty * 16 + tx;
    const int lm = tid >> 2;
    const int lk = (tid & 3) * 4;
    const int Keff = row0 + BM;             // attn[r, j>r] == 0
    float acc[4][4] = {};
    for (int k0 = 0; k0 < Keff; k0 += BK) {
        float4 a4 = *(const float4*)&A[(size_t)(row0 + lm) * TT + k0 + lk];
        As[lk + 0][lm] = a4.x; As[lk + 1][lm] = a4.y;
        As[lk + 2][lm] = a4.z; As[lk + 3][lm] = a4.w;
        { // B: 16 k x 64 n, n-contiguous
            int kk = tid >> 4, n = (tid & 15) * 4;
            float4 b4 = *(const float4*)&Bp[(size_t)(k0 + kk) * DD + n];
            Bs[kk][n + 0] = b4.x; Bs[kk][n + 1] = b4.y;
            Bs[kk][n + 2] = b4.z; Bs[kk][n + 3] = b4.w;
        }
        __syncthreads();
#pragma unroll
        for (int kk = 0; kk < BK; kk++) {
            float a[4], bb[4];
#pragma unroll
            for (int i = 0; i < 4; i++) a[i] = As[kk][ty * 4 + i];
#pragma unroll
            for (int j = 0; j < 4; j++) bb[j] = Bs[kk][tx * 4 + j];
#pragma unroll
            for (int i = 0; i < 4; i++)
#pragma unroll
                for (int j = 0; j < 4; j++) acc[i][j] = fmaf(a[i], bb[j], acc[i][j]);
        }
        __syncthreads();
    }
#pragma unroll
    for (int i = 0; i < 4; i++)
#pragma unroll
        for (int j = 0; j < 4; j++)
            C[(size_t)(row0 + ty * 4 + i) * DD + tx * 4 + j] = acc[i][j];
}

// ---------------------------------------------------------------------------
extern "C" void kernel_launch(void* const* d_in, const int* in_sizes, int n_in,
                              void* d_out, int out_size) {
    const float* x  = (const float*)d_in[0];
    const float* Wq = (const float*)d_in[1];
    const float* Wk = (const float*)d_in[2];
    const float* Wv = (const float*)d_in[3];
    const float* Wo = (const float*)d_in[4];
    float* out = (float*)d_out;

    const size_t out_elems  = (size_t)BB * TT * DD;         // 8,388,608
    const size_t attn_elems = (size_t)BB * HH * TT * TT;    // 268,435,456

    float* attn;
    if ((size_t)out_size >= out_elems + attn_elems) {
        attn = out + out_elems;            // tuple (out, attn) flattened
    } else {
        float* p;
        cudaGetSymbolAddress((void**)&p, g_attn);
        attn = p;
    }
    float *q, *k, *v, *ctx;
    cudaGetSymbolAddress((void**)&q,   g_q);
    cudaGetSymbolAddress((void**)&k,   g_k);
    cudaGetSymbolAddress((void**)&v,   g_v);
    cudaGetSymbolAddress((void**)&ctx, g_ctx);

    dim3 blk(16, 16);
    dim3 gproj(DD / BN, MM / BM);       // 16 x 128
    gemm_abt<<<gproj, blk>>>(x, Wq, q, DD, DD, DD, DD);
    gemm_abt<<<gproj, blk>>>(x, Wk, k, DD, DD, DD, DD);
    gemm_abt<<<gproj, blk>>>(x, Wv, v, DD, DD, DD, DD);

    dim3 gsc(TT / BN, TT / BM, BB * HH);  // 32 x 32 x 64 (half early-exit)
    scores_kernel<<<gsc, blk>>>(q, k, attn);

    softmax_kernel<<<BB * HH * TT, 256>>>(attn);

    dim3 gctx(1, TT / BM, BB * HH);       // 1 x 32 x 64
    ctx_kernel<<<gctx, blk>>>(attn, v, ctx);

    gemm_abt<<<gproj, blk>>>(ctx, Wo, out, DD, DD, DD, DD);
}